// round 13
// baseline (speedup 1.0000x reference)
#include <cuda_runtime.h>
#include <cstdint>

// Problem constants
#define BB   16
#define NN   8192
#define CIN  3
#define HID  64
#define DD   256
#define KK   4
#define GHID 128
#define DOUT 128
#define TILE 128
#define NT   (NN / TILE)            // 64 tiles
#define SLOTS (NT * BB)             // 1024 (tile,b) slots per branch
#define BLKS_PER_KB 74
#define PBLOCKS (BLKS_PER_KB * KK)  // 296 = 2 CTAs x 148 SMs

// dynamic smem layout (bytes)
#define OFF_W2   0                  // [HID][DD] floats = 64 KB
#define OFF_HT   65536              // [HID][TILE] floats = 32 KB
#define OFF_X0   98304              // [TILE]
#define OFF_X1   98816
#define OFF_X2   99328
#define OFF_IDX  99840              // [TILE] int
#define OFF_W1   100352             // [CIN*HID]
#define OFF_B1   101120             // [HID]
#define K2_SMEM  101376

// ---------------- device scratch (static, no allocations) ----------------
__device__ int      g_cnt[BB * KK];
__device__ int      g_idx[BB * KK * NN];       // per (b,k) index lists
__device__ unsigned g_maxu[BB * DD];           // flipped-float max slots

// ---------------- helpers ----------------
__device__ __forceinline__ float gelu_exact(float x) {
    return 0.5f * x * (1.0f + erff(x * 0.7071067811865476f));
}

// Fast exact-GELU for small |v|: odd Taylor series of erf(v/sqrt(2))
// truncated at s^3. Alternating series => |rel err| < 1.3e-6 for |v| <= 0.5.
// Data here has |v| <= ~0.2 (sigma ~ 0.035), so the erff fallback never
// fires in practice but keeps correctness unconditional.
__device__ __forceinline__ float gelu_fast(float v) {
    float s = v * v;
    if (s > 0.25f) {                       // |v| > 0.5 : exact path (cold)
        return 0.5f * v * (1.0f + erff(v * 0.7071067811865476f));
    }
    float p = fmaf(s, -1.0f / 336.0f, 1.0f / 40.0f);
    p = fmaf(s, p, -1.0f / 6.0f);
    p = fmaf(s, p, 1.0f);
    // gelu = 0.5v + 0.3989422804*v^2*p  (0.3989.. = 1/sqrt(2*pi))
    return fmaf(0.3989422804014327f * v * v, p, 0.5f * v);
}

__device__ __forceinline__ unsigned long long fma2(unsigned long long a,
                                                   unsigned long long b,
                                                   unsigned long long c) {
    unsigned long long d;
    asm("fma.rn.f32x2 %0, %1, %2, %3;" : "=l"(d) : "l"(a), "l"(b), "l"(c));
    return d;
}

__device__ __forceinline__ unsigned long long dup2(float v) {
    unsigned long long r;
    asm("mov.b64 %0, {%1, %1};" : "=l"(r) : "f"(v));
    return r;
}

__device__ __forceinline__ void unpack2(unsigned long long v, float& lo, float& hi) {
    asm("mov.b64 {%0, %1}, %2;" : "=f"(lo), "=f"(hi) : "l"(v));
}

// order-preserving float -> uint mapping (for exact atomic max)
__device__ __forceinline__ unsigned flip_f32(float f) {
    unsigned u = __float_as_uint(f);
    return (u & 0x80000000u) ? ~u : (u | 0x80000000u);
}
__device__ __forceinline__ float unflip_f32(unsigned e) {
    unsigned u = (e & 0x80000000u) ? (e ^ 0x80000000u) : ~e;
    return __uint_as_float(u);
}

// ---------------- K0: reset scratch ----------------
__global__ void k0_init() {
    int i = blockIdx.x * 256 + threadIdx.x;
    if (i < BB * KK) g_cnt[i] = 0;
    if (i < BB * DD) g_maxu[i] = 0u;   // below all finite flipped floats
}

// ---------------- K1: argmax classify + compaction ----------------
__global__ void k1_classify(const float* __restrict__ lab) {
    __shared__ int scnt[KK];
    __shared__ int sbase[KK];
    int t   = threadIdx.x;
    int gid = blockIdx.x * 256 + t;
    int b   = gid / NN;
    int n   = gid % NN;

    if (t < KK) scnt[t] = 0;
    __syncthreads();

    const float* lb = lab + (size_t)b * KK * NN + n;
    float l0 = lb[0], l1 = lb[NN], l2 = lb[2 * NN], l3 = lb[3 * NN];
    int k = 0; float best = l0;
    if (l1 > best) { best = l1; k = 1; }
    if (l2 > best) { best = l2; k = 2; }
    if (l3 > best) { best = l3; k = 3; }

    int pos = atomicAdd(&scnt[k], 1);
    __syncthreads();
    if (t < KK) sbase[t] = atomicAdd(&g_cnt[b * KK + t], scnt[t]);
    __syncthreads();
    g_idx[(b * KK + k) * NN + sbase[k] + pos] = n;
}

// ---------------- K2: persistent, branch-pinned, W2 in SMEM ----------------
// Identical to R12 except phase-1 uses gelu_fast (polynomial erf) instead of
// erff — phase-1 was ~half the kernel's issue bandwidth.
__global__ __launch_bounds__(256, 2)
void k2_main(const float* __restrict__ x,
             const float* __restrict__ W1, const float* __restrict__ b1,
             const float* __restrict__ W2, const float* __restrict__ b2) {
    extern __shared__ __align__(16) char smem[];
    float* W2s              = reinterpret_cast<float*>(smem + OFF_W2);
    float (*sh_ht)[TILE]    = reinterpret_cast<float(*)[TILE]>(smem + OFF_HT);
    float* sh_x0            = reinterpret_cast<float*>(smem + OFF_X0);
    float* sh_x1            = reinterpret_cast<float*>(smem + OFF_X1);
    float* sh_x2            = reinterpret_cast<float*>(smem + OFF_X2);
    int*   sh_idx           = reinterpret_cast<int*>  (smem + OFF_IDX);
    float* sh_w1            = reinterpret_cast<float*>(smem + OFF_W1);
    float* sh_b1            = reinterpret_cast<float*>(smem + OFF_B1);

    const int t     = threadIdx.x;
    const int kb    = blockIdx.x & 3;
    const int slot0 = blockIdx.x >> 2;       // 0..73
    const int dtile = t >> 3;                // 0..31
    const int prow  = t & 7;                 // 0..7
    const int d0    = dtile * 8;

    // one-time per-block loads: W2[kb] (coalesced 16B), W1[kb], b1[kb]
    {
        const float4* src = reinterpret_cast<const float4*>(W2 + (size_t)kb * HID * DD);
        float4* dst = reinterpret_cast<float4*>(W2s);
        #pragma unroll
        for (int i = 0; i < (HID * DD / 4) / 256; i++)
            dst[i * 256 + t] = src[i * 256 + t];
        if (t < CIN * HID) sh_w1[t] = W1[kb * CIN * HID + t];
        if (t < HID)       sh_b1[t] = b1[kb * HID + t];
    }
    __syncthreads();

    const float* wbase = W2s + d0;

    for (int it = slot0; it < SLOTS; it += BLKS_PER_KB) {
        const int tile = it >> 4;
        const int b    = it & 15;

        const int cnt   = g_cnt[b * KK + kb];
        const int start = tile * TILE;
        if (start >= cnt) continue;           // block-uniform branch
        const int npts = min(TILE, cnt - start);

        __syncthreads();   // previous item's phase-2 reads done before overwrite

        if (t < TILE && t < npts) sh_idx[t] = g_idx[(b * KK + kb) * NN + start + t];
        __syncthreads();

        if (t < npts) {
            int n = sh_idx[t];
            const float* xb = x + (size_t)b * CIN * NN;
            sh_x0[t] = xb[n];
            sh_x1[t] = xb[NN + n];
            sh_x2[t] = xb[2 * NN + n];
        }
        __syncthreads();

        // ---- phase 1: lane = point, jg = t>>5 covers 8 j's; zero-fill tail
        {
            const int lane = t & 31;
            const int jg   = t >> 5;            // 0..7
            #pragma unroll
            for (int pass = 0; pass < TILE / 32; pass++) {
                int pp = pass * 32 + lane;
                if (pp < npts) {
                    float x0 = sh_x0[pp], x1 = sh_x1[pp], x2 = sh_x2[pp];
                    #pragma unroll
                    for (int jj = 0; jj < 8; jj++) {
                        int j = jg * 8 + jj;
                        float v = fmaf(x0, sh_w1[j],
                                  fmaf(x1, sh_w1[HID + j],
                                  fmaf(x2, sh_w1[2 * HID + j], sh_b1[j])));
                        sh_ht[j][pp] = gelu_fast(v);
                    }
                } else {
                    #pragma unroll
                    for (int jj = 0; jj < 8; jj++)
                        sh_ht[jg * 8 + jj][pp] = 0.0f;
                }
            }
        }
        __syncthreads();

        // ---- phase 2: 8 dims x 4 points per thread, 4 passes, pipelined kk
        float mx[8];
        #pragma unroll
        for (int c = 0; c < 8; c++) mx[c] = -3.402823466e38f;

        #pragma unroll 1
        for (int pass = 0; pass < TILE / 32; pass++) {
            const int p0 = pass * 32 + prow * 4;
            const float* hcol = &sh_ht[0][p0];

            unsigned long long acc[4][4];   // [point][dim-pair]
            #pragma unroll
            for (int p = 0; p < 4; p++)
                #pragma unroll
                for (int c = 0; c < 4; c++) acc[p][c] = 0ull;

            // prologue: load kk = 0 (all smem)
            float4 ha      = *reinterpret_cast<const float4*>(hcol);
            ulonglong2 w03 = *reinterpret_cast<const ulonglong2*>(wbase);
            ulonglong2 w47 = *reinterpret_cast<const ulonglong2*>(wbase + 4);

            #pragma unroll 1
            for (int kk = 0; kk < HID - 1; kk++) {
                const float4 hc     = ha;
                const ulonglong2 wA = w03;
                const ulonglong2 wB = w47;
                // prefetch next iteration (overlaps with the FMAs below)
                ha  = *reinterpret_cast<const float4*>(hcol + (size_t)(kk + 1) * TILE);
                w03 = *reinterpret_cast<const ulonglong2*>(wbase + (size_t)(kk + 1) * DD);
                w47 = *reinterpret_cast<const ulonglong2*>(wbase + (size_t)(kk + 1) * DD + 4);

                const unsigned long long h0 = dup2(hc.x), h1 = dup2(hc.y),
                                         h2 = dup2(hc.z), h3 = dup2(hc.w);
                acc[0][0] = fma2(h0, wA.x, acc[0][0]);
                acc[0][1] = fma2(h0, wA.y, acc[0][1]);
                acc[0][2] = fma2(h0, wB.x, acc[0][2]);
                acc[0][3] = fma2(h0, wB.y, acc[0][3]);
                acc[1][0] = fma2(h1, wA.x, acc[1][0]);
                acc[1][1] = fma2(h1, wA.y, acc[1][1]);
                acc[1][2] = fma2(h1, wB.x, acc[1][2]);
                acc[1][3] = fma2(h1, wB.y, acc[1][3]);
                acc[2][0] = fma2(h2, wA.x, acc[2][0]);
                acc[2][1] = fma2(h2, wA.y, acc[2][1]);
                acc[2][2] = fma2(h2, wB.x, acc[2][2]);
                acc[2][3] = fma2(h2, wB.y, acc[2][3]);
                acc[3][0] = fma2(h3, wA.x, acc[3][0]);
                acc[3][1] = fma2(h3, wA.y, acc[3][1]);
                acc[3][2] = fma2(h3, wB.x, acc[3][2]);
                acc[3][3] = fma2(h3, wB.y, acc[3][3]);
            }
            // epilogue: kk = HID-1
            {
                const unsigned long long h0 = dup2(ha.x), h1 = dup2(ha.y),
                                         h2 = dup2(ha.z), h3 = dup2(ha.w);
                acc[0][0] = fma2(h0, w03.x, acc[0][0]);
                acc[0][1] = fma2(h0, w03.y, acc[0][1]);
                acc[0][2] = fma2(h0, w47.x, acc[0][2]);
                acc[0][3] = fma2(h0, w47.y, acc[0][3]);
                acc[1][0] = fma2(h1, w03.x, acc[1][0]);
                acc[1][1] = fma2(h1, w03.y, acc[1][1]);
                acc[1][2] = fma2(h1, w47.x, acc[1][2]);
                acc[1][3] = fma2(h1, w47.y, acc[1][3]);
                acc[2][0] = fma2(h2, w03.x, acc[2][0]);
                acc[2][1] = fma2(h2, w03.y, acc[2][1]);
                acc[2][2] = fma2(h2, w47.x, acc[2][2]);
                acc[2][3] = fma2(h2, w47.y, acc[2][3]);
                acc[3][0] = fma2(h3, w03.x, acc[3][0]);
                acc[3][1] = fma2(h3, w03.y, acc[3][1]);
                acc[3][2] = fma2(h3, w47.x, acc[3][2]);
                acc[3][3] = fma2(h3, w47.y, acc[3][3]);
            }

            // fold valid points of this pass into per-dim running max
            #pragma unroll
            for (int p = 0; p < 4; p++) {
                if (p0 + p < npts) {
                    #pragma unroll
                    for (int c = 0; c < 4; c++) {
                        float lo, hi; unpack2(acc[p][c], lo, hi);
                        mx[2 * c]     = fmaxf(mx[2 * c],     lo);
                        mx[2 * c + 1] = fmaxf(mx[2 * c + 1], hi);
                    }
                }
            }
        }

        // warp butterfly over prow bits (lanes sharing a dtile are adjacent)
        #pragma unroll
        for (int s = 1; s < 8; s <<= 1)
            #pragma unroll
            for (int c = 0; c < 8; c++)
                mx[c] = fmaxf(mx[c], __shfl_xor_sync(0xffffffffu, mx[c], s));

        if (prow == 0) {
            #pragma unroll
            for (int c = 0; c < 8; c++) {
                float v = mx[c] + b2[kb * DD + d0 + c];  // bias hoisted past max
                atomicMax(&g_maxu[b * DD + d0 + c], flip_f32(v));
            }
        }
    }
}

// ---------------- K3: global MLP on per-batch max ----------------
__global__ __launch_bounds__(1024, 1)
void k3_head(const float* __restrict__ Wg1, const float* __restrict__ bg1,
             const float* __restrict__ Wg2, const float* __restrict__ bg2,
             float* __restrict__ out) {
    __shared__ float sg[DD];
    __shared__ float part[1024];
    __shared__ float shg[GHID];
    const int b   = blockIdx.x;
    const int tid = threadIdx.x;
    const int t   = tid & 127;     // output unit
    const int g   = tid >> 7;      // j-split group 0..7

    if (tid < DD) sg[tid] = unflip_f32(g_maxu[b * DD + tid]);
    __syncthreads();

    // layer 1: 256 -> 128, each thread covers 32 j's
    {
        float acc = 0.0f;
        const int j0 = g * 32;
        #pragma unroll 16
        for (int j = 0; j < 32; j++)
            acc = fmaf(sg[j0 + j], Wg1[(j0 + j) * GHID + t], acc);
        part[tid] = acc;
    }
    __syncthreads();
    if (tid < GHID) {
        float v = bg1[tid];
        #pragma unroll
        for (int gg = 0; gg < 8; gg++) v += part[tid + 128 * gg];
        shg[tid] = gelu_exact(v);
    }
    __syncthreads();

    // layer 2: 128 -> 128, each thread covers 16 j's
    {
        float acc = 0.0f;
        const int j0 = g * 16;
        #pragma unroll 16
        for (int j = 0; j < 16; j++)
            acc = fmaf(shg[j0 + j], Wg2[(j0 + j) * DOUT + t], acc);
        part[tid] = acc;
    }
    __syncthreads();
    if (tid < DOUT) {
        float v = bg2[tid];
        #pragma unroll
        for (int gg = 0; gg < 8; gg++) v += part[tid + 128 * gg];
        out[b * DOUT + tid] = v;
    }
}

// ---------------- launch ----------------
extern "C" void kernel_launch(void* const* d_in, const int* in_sizes, int n_in,
                              void* d_out, int out_size) {
    const float* x     = (const float*)d_in[0];
    const float* xlab  = (const float*)d_in[1];
    const float* W1    = (const float*)d_in[2];
    const float* b1    = (const float*)d_in[3];
    const float* W2    = (const float*)d_in[4];
    const float* b2    = (const float*)d_in[5];
    const float* Wg1   = (const float*)d_in[6];
    const float* bg1   = (const float*)d_in[7];
    const float* Wg2   = (const float*)d_in[8];
    const float* bg2   = (const float*)d_in[9];
    float* out = (float*)d_out;

    // opt-in to 99 KB dynamic smem for k2 (idempotent; attribute set, not an
    // allocation — legal under the harness rules and during graph capture)
    cudaFuncSetAttribute(k2_main, cudaFuncAttributeMaxDynamicSharedMemorySize,
                         K2_SMEM);

    k0_init<<<(BB * DD + 255) / 256, 256>>>();
    k1_classify<<<(BB * NN) / 256, 256>>>(xlab);
    k2_main<<<PBLOCKS, 256, K2_SMEM>>>(x, W1, b1, W2, b2);
    k3_head<<<BB, 1024>>>(Wg1, bg1, Wg2, bg2, out);
}

// round 14
// speedup vs baseline: 2.2476x; 2.2476x over previous
#include <cuda_runtime.h>
#include <cuda_bf16.h>
#include <cstdint>

// Problem constants
#define BB   16
#define NN   8192
#define CIN  3
#define HID  64
#define DD   256
#define KK   4
#define GHID 128
#define DOUT 128
#define TILE 64
#define NT   (NN / TILE)            // 128 tiles
#define SLOTS (NT * BB)             // 2048 (tile,b) slots per branch
#define BLKS_PER_KB 74
#define PBLOCKS (BLKS_PER_KB * KK)  // 296 = 2 CTAs x 148 SMs

#define RSTRIDE 72                  // padded row stride in bf16 units (144 B)

// dynamic smem layout (bytes)
#define OFF_W2HI 0                      // [DD][RSTRIDE] bf16 = 36864
#define OFF_W2LO 36864                  // 36864
#define OFF_HHI  73728                  // [TILE][RSTRIDE] bf16 = 9216
#define OFF_HLO  82944                  // 9216
#define OFF_X0   92160                  // [TILE] float
#define OFF_X1   92416
#define OFF_X2   92672
#define OFF_IDX  92928                  // [TILE] int
#define OFF_W1   93184                  // [CIN*HID] float
#define OFF_B1   93952                  // [HID] float
#define K2_SMEM  94208                  // 92 KB -> 2 CTAs = 184 KB/SM

// ---------------- device scratch (static, no allocations) ----------------
__device__ int      g_cnt[BB * KK];
__device__ int      g_idx[BB * KK * NN];       // per (b,k) index lists
__device__ unsigned g_maxu[BB * DD];           // flipped-float max slots

// ---------------- helpers ----------------
__device__ __forceinline__ float gelu_exact(float x) {
    return 0.5f * x * (1.0f + erff(x * 0.7071067811865476f));
}

// Fast exact-GELU for small |v| (Taylor of erf, rel err < 1.3e-6 for |v|<=0.5)
__device__ __forceinline__ float gelu_fast(float v) {
    float s = v * v;
    if (s > 0.25f) {
        return 0.5f * v * (1.0f + erff(v * 0.7071067811865476f));
    }
    float p = fmaf(s, -1.0f / 336.0f, 1.0f / 40.0f);
    p = fmaf(s, p, -1.0f / 6.0f);
    p = fmaf(s, p, 1.0f);
    return fmaf(0.3989422804014327f * v * v, p, 0.5f * v);
}

__device__ __forceinline__ unsigned pack_bf16(float a, float b) {
    unsigned short ua = __bfloat16_as_ushort(__float2bfloat16(a));
    unsigned short ub = __bfloat16_as_ushort(__float2bfloat16(b));
    return (unsigned)ua | ((unsigned)ub << 16);
}

// m16n8k16 row.col bf16 MMA, fp32 accumulate (standard sm_80+ fragment layout)
__device__ __forceinline__ void mma_bf16(float* c,
                                         unsigned a0, unsigned a1,
                                         unsigned a2, unsigned a3,
                                         unsigned b0, unsigned b1) {
    asm volatile(
        "mma.sync.aligned.m16n8k16.row.col.f32.bf16.bf16.f32 "
        "{%0,%1,%2,%3}, {%4,%5,%6,%7}, {%8,%9}, {%0,%1,%2,%3};\n"
        : "+f"(c[0]), "+f"(c[1]), "+f"(c[2]), "+f"(c[3])
        : "r"(a0), "r"(a1), "r"(a2), "r"(a3), "r"(b0), "r"(b1));
}

// order-preserving float -> uint mapping (for exact atomic max)
__device__ __forceinline__ unsigned flip_f32(float f) {
    unsigned u = __float_as_uint(f);
    return (u & 0x80000000u) ? ~u : (u | 0x80000000u);
}
__device__ __forceinline__ float unflip_f32(unsigned e) {
    unsigned u = (e & 0x80000000u) ? (e ^ 0x80000000u) : ~e;
    return __uint_as_float(u);
}

// ---------------- K0: reset scratch ----------------
__global__ void k0_init() {
    int i = blockIdx.x * 256 + threadIdx.x;
    if (i < BB * KK) g_cnt[i] = 0;
    if (i < BB * DD) g_maxu[i] = 0u;   // below all finite flipped floats
}

// ---------------- K1: argmax classify + compaction ----------------
__global__ void k1_classify(const float* __restrict__ lab) {
    __shared__ int scnt[KK];
    __shared__ int sbase[KK];
    int t   = threadIdx.x;
    int gid = blockIdx.x * 256 + t;
    int b   = gid / NN;
    int n   = gid % NN;

    if (t < KK) scnt[t] = 0;
    __syncthreads();

    const float* lb = lab + (size_t)b * KK * NN + n;
    float l0 = lb[0], l1 = lb[NN], l2 = lb[2 * NN], l3 = lb[3 * NN];
    int k = 0; float best = l0;
    if (l1 > best) { best = l1; k = 1; }
    if (l2 > best) { best = l2; k = 2; }
    if (l3 > best) { best = l3; k = 3; }

    int pos = atomicAdd(&scnt[k], 1);
    __syncthreads();
    if (t < KK) sbase[t] = atomicAdd(&g_cnt[b * KK + t], scnt[t]);
    __syncthreads();
    g_idx[(b * KK + k) * NN + sbase[k] + pos] = n;
}

// ---------------- K2: persistent, branch-pinned, TENSOR phase 2 ----------------
// 296 blocks (2 CTAs x 148 SMs), 256 threads, kb fixed per block.
// Once per block: W2[kb] split to bf16 hi/lo, TRANSPOSED [d][k] in smem.
// Per item (64 pts): phase 1 computes h=gelu(xW1+b1), splits to bf16 hi/lo
// [pt][k] (rows padded to 72 bf16 -> conflict-free quad frag loads).
// Phase 2: warp w owns dims w*32..+31; 4 m-tiles of 16 rows; per m-tile
// 4 ksteps x 4 nfrags x 3 split-MMAs (AhiBhi + AhiBlo + AloBhi) into fp32
// frags; fold row-masked max; butterfly over same-column lanes; atomicMax.
__global__ __launch_bounds__(256, 2)
void k2_main(const float* __restrict__ x,
             const float* __restrict__ W1, const float* __restrict__ b1,
             const float* __restrict__ W2g, const float* __restrict__ b2) {
    extern __shared__ __align__(16) char smem[];
    __nv_bfloat16* w2hi = reinterpret_cast<__nv_bfloat16*>(smem + OFF_W2HI);
    __nv_bfloat16* w2lo = reinterpret_cast<__nv_bfloat16*>(smem + OFF_W2LO);
    float* sh_x0 = reinterpret_cast<float*>(smem + OFF_X0);
    float* sh_x1 = reinterpret_cast<float*>(smem + OFF_X1);
    float* sh_x2 = reinterpret_cast<float*>(smem + OFF_X2);
    int*   sh_idx = reinterpret_cast<int*> (smem + OFF_IDX);
    float* sh_w1 = reinterpret_cast<float*>(smem + OFF_W1);
    float* sh_b1 = reinterpret_cast<float*>(smem + OFF_B1);

    const int t     = threadIdx.x;
    const int kb    = blockIdx.x & 3;
    const int slot0 = blockIdx.x >> 2;       // 0..73
    const int w     = t >> 5;                // warp 0..7
    const int lane  = t & 31;
    const int lq    = lane >> 2;             // 0..7 (row group / n col)
    const int lr    = lane & 3;              // 0..3 (k/col pair select)
    const int d0    = w * 32;

    // ---- once per block: W1/b1 + W2 split->bf16, transposed [d][k] ----
    {
        const int d = t;                     // 0..255
        #pragma unroll 8
        for (int k = 0; k < HID; k++) {
            float wv = W2g[((size_t)kb * HID + k) * DD + d];
            __nv_bfloat16 hi = __float2bfloat16(wv);
            float lo = wv - __bfloat162float(hi);
            w2hi[d * RSTRIDE + k] = hi;
            w2lo[d * RSTRIDE + k] = __float2bfloat16(lo);
        }
        if (t < CIN * HID) sh_w1[t] = W1[kb * CIN * HID + t];
        if (t < HID)       sh_b1[t] = b1[kb * HID + t];
    }
    __syncthreads();

    for (int it = slot0; it < SLOTS; it += BLKS_PER_KB) {
        const int tile = it >> 4;            // 0..127
        const int b    = it & 15;

        const int cnt   = g_cnt[b * KK + kb];
        const int start = tile * TILE;
        if (start >= cnt) continue;          // block-uniform branch
        const int npts = min(TILE, cnt - start);

        __syncthreads();   // previous item's phase-2 reads done before overwrite

        if (t < TILE && t < npts) sh_idx[t] = g_idx[(b * KK + kb) * NN + start + t];
        __syncthreads();

        if (t < npts) {
            int n = sh_idx[t];
            const float* xb = x + (size_t)b * CIN * NN;
            sh_x0[t] = xb[n];
            sh_x1[t] = xb[NN + n];
            sh_x2[t] = xb[2 * NN + n];
        }
        __syncthreads();

        // ---- phase 1: pt = t&63, jhalf = t>>6 covers 16 j's; bf16 split
        {
            const int pt = t & 63;
            const int j0 = (t >> 6) * 16;
            unsigned* hhi = reinterpret_cast<unsigned*>(smem + OFF_HHI) + (pt * RSTRIDE + j0) / 2;
            unsigned* hlo = reinterpret_cast<unsigned*>(smem + OFF_HLO) + (pt * RSTRIDE + j0) / 2;
            if (pt < npts) {
                float x0 = sh_x0[pt], x1 = sh_x1[pt], x2 = sh_x2[pt];
                #pragma unroll
                for (int p = 0; p < 8; p++) {
                    int ja = j0 + 2 * p, jb = ja + 1;
                    float va = fmaf(x0, sh_w1[ja],
                               fmaf(x1, sh_w1[HID + ja],
                               fmaf(x2, sh_w1[2 * HID + ja], sh_b1[ja])));
                    float vb = fmaf(x0, sh_w1[jb],
                               fmaf(x1, sh_w1[HID + jb],
                               fmaf(x2, sh_w1[2 * HID + jb], sh_b1[jb])));
                    va = gelu_fast(va);
                    vb = gelu_fast(vb);
                    __nv_bfloat16 ha = __float2bfloat16(va);
                    __nv_bfloat16 hb = __float2bfloat16(vb);
                    float la = va - __bfloat162float(ha);
                    float lb = vb - __bfloat162float(hb);
                    hhi[p] = (unsigned)__bfloat16_as_ushort(ha)
                           | ((unsigned)__bfloat16_as_ushort(hb) << 16);
                    hlo[p] = pack_bf16(la, lb);
                }
            } else {
                #pragma unroll
                for (int p = 0; p < 8; p++) { hhi[p] = 0u; hlo[p] = 0u; }
            }
        }
        __syncthreads();

        // ---- phase 2: tensor MMA, warp-local ----
        const char* hhiB = smem + OFF_HHI;
        const char* hloB = smem + OFF_HLO;
        const char* whiB = smem + OFF_W2HI;
        const char* wloB = smem + OFF_W2LO;

        float mxf[4][4];
        #pragma unroll
        for (int nf = 0; nf < 4; nf++)
            #pragma unroll
            for (int c = 0; c < 4; c++) mxf[nf][c] = -3.402823466e38f;

        #pragma unroll 1
        for (int mtile = 0; mtile < 4; mtile++) {
            const int r0 = mtile * 16 + lq;      // rows this lane covers
            const int r1 = r0 + 8;

            float acc[4][4];
            #pragma unroll
            for (int nf = 0; nf < 4; nf++)
                #pragma unroll
                for (int c = 0; c < 4; c++) acc[nf][c] = 0.0f;

            #pragma unroll
            for (int ks = 0; ks < 4; ks++) {
                const int c0 = ks * 16 + 2 * lr;     // k col pair base (even)
                // A frags: (r, c) pairs; b32 = bf16x2 of (k, k+1)
                unsigned ah0 = *reinterpret_cast<const unsigned*>(hhiB + (r0 * RSTRIDE + c0) * 2);
                unsigned ah1 = *reinterpret_cast<const unsigned*>(hhiB + (r1 * RSTRIDE + c0) * 2);
                unsigned ah2 = *reinterpret_cast<const unsigned*>(hhiB + (r0 * RSTRIDE + c0 + 8) * 2);
                unsigned ah3 = *reinterpret_cast<const unsigned*>(hhiB + (r1 * RSTRIDE + c0 + 8) * 2);
                unsigned al0 = *reinterpret_cast<const unsigned*>(hloB + (r0 * RSTRIDE + c0) * 2);
                unsigned al1 = *reinterpret_cast<const unsigned*>(hloB + (r1 * RSTRIDE + c0) * 2);
                unsigned al2 = *reinterpret_cast<const unsigned*>(hloB + (r0 * RSTRIDE + c0 + 8) * 2);
                unsigned al3 = *reinterpret_cast<const unsigned*>(hloB + (r1 * RSTRIDE + c0 + 8) * 2);

                #pragma unroll
                for (int nf = 0; nf < 4; nf++) {
                    const int n = d0 + nf * 8 + lq;  // this lane's B column
                    unsigned bh0 = *reinterpret_cast<const unsigned*>(whiB + (n * RSTRIDE + c0) * 2);
                    unsigned bh1 = *reinterpret_cast<const unsigned*>(whiB + (n * RSTRIDE + c0 + 8) * 2);
                    unsigned bl0 = *reinterpret_cast<const unsigned*>(wloB + (n * RSTRIDE + c0) * 2);
                    unsigned bl1 = *reinterpret_cast<const unsigned*>(wloB + (n * RSTRIDE + c0 + 8) * 2);
                    mma_bf16(acc[nf], ah0, ah1, ah2, ah3, bh0, bh1);
                    mma_bf16(acc[nf], ah0, ah1, ah2, ah3, bl0, bl1);
                    mma_bf16(acc[nf], al0, al1, al2, al3, bh0, bh1);
                }
            }

            // fold with row masking (c0,c1 -> row r0; c2,c3 -> row r1)
            const bool v0 = (r0 < npts);
            const bool v1 = (r1 < npts);
            #pragma unroll
            for (int nf = 0; nf < 4; nf++) {
                if (v0) {
                    mxf[nf][0] = fmaxf(mxf[nf][0], acc[nf][0]);
                    mxf[nf][1] = fmaxf(mxf[nf][1], acc[nf][1]);
                }
                if (v1) {
                    mxf[nf][2] = fmaxf(mxf[nf][2], acc[nf][2]);
                    mxf[nf][3] = fmaxf(mxf[nf][3], acc[nf][3]);
                }
            }
        }

        // combine row-halves, butterfly over lanes with equal column (xor 4,8,16)
        float m0[4], m1[4];
        #pragma unroll
        for (int nf = 0; nf < 4; nf++) {
            m0[nf] = fmaxf(mxf[nf][0], mxf[nf][2]);   // col 2*lr
            m1[nf] = fmaxf(mxf[nf][1], mxf[nf][3]);   // col 2*lr+1
        }
        #pragma unroll
        for (int s = 4; s < 32; s <<= 1) {
            #pragma unroll
            for (int nf = 0; nf < 4; nf++) {
                m0[nf] = fmaxf(m0[nf], __shfl_xor_sync(0xffffffffu, m0[nf], s));
                m1[nf] = fmaxf(m1[nf], __shfl_xor_sync(0xffffffffu, m1[nf], s));
            }
        }
        if (lane < 4) {
            #pragma unroll
            for (int nf = 0; nf < 4; nf++) {
                int d = d0 + nf * 8 + 2 * lane;
                float va = m0[nf] + b2[kb * DD + d];
                float vb = m1[nf] + b2[kb * DD + d + 1];
                atomicMax(&g_maxu[b * DD + d],     flip_f32(va));
                atomicMax(&g_maxu[b * DD + d + 1], flip_f32(vb));
            }
        }
    }
}

// ---------------- K3: global MLP on per-batch max ----------------
__global__ __launch_bounds__(1024, 1)
void k3_head(const float* __restrict__ Wg1, const float* __restrict__ bg1,
             const float* __restrict__ Wg2, const float* __restrict__ bg2,
             float* __restrict__ out) {
    __shared__ float sg[DD];
    __shared__ float part[1024];
    __shared__ float shg[GHID];
    const int b   = blockIdx.x;
    const int tid = threadIdx.x;
    const int t   = tid & 127;     // output unit
    const int g   = tid >> 7;      // j-split group 0..7

    if (tid < DD) sg[tid] = unflip_f32(g_maxu[b * DD + tid]);
    __syncthreads();

    // layer 1: 256 -> 128, each thread covers 32 j's
    {
        float acc = 0.0f;
        const int j0 = g * 32;
        #pragma unroll 16
        for (int j = 0; j < 32; j++)
            acc = fmaf(sg[j0 + j], Wg1[(j0 + j) * GHID + t], acc);
        part[tid] = acc;
    }
    __syncthreads();
    if (tid < GHID) {
        float v = bg1[tid];
        #pragma unroll
        for (int gg = 0; gg < 8; gg++) v += part[tid + 128 * gg];
        shg[tid] = gelu_exact(v);
    }
    __syncthreads();

    // layer 2: 128 -> 128, each thread covers 16 j's
    {
        float acc = 0.0f;
        const int j0 = g * 16;
        #pragma unroll 16
        for (int j = 0; j < 16; j++)
            acc = fmaf(shg[j0 + j], Wg2[(j0 + j) * DOUT + t], acc);
        part[tid] = acc;
    }
    __syncthreads();
    if (tid < DOUT) {
        float v = bg2[tid];
        #pragma unroll
        for (int gg = 0; gg < 8; gg++) v += part[tid + 128 * gg];
        out[b * DOUT + tid] = v;
    }
}

// ---------------- launch ----------------
extern "C" void kernel_launch(void* const* d_in, const int* in_sizes, int n_in,
                              void* d_out, int out_size) {
    const float* x     = (const float*)d_in[0];
    const float* xlab  = (const float*)d_in[1];
    const float* W1    = (const float*)d_in[2];
    const float* b1    = (const float*)d_in[3];
    const float* W2    = (const float*)d_in[4];
    const float* b2    = (const float*)d_in[5];
    const float* Wg1   = (const float*)d_in[6];
    const float* bg1   = (const float*)d_in[7];
    const float* Wg2   = (const float*)d_in[8];
    const float* bg2   = (const float*)d_in[9];
    float* out = (float*)d_out;

    // opt-in to 92 KB dynamic smem for k2 (attribute set, not an allocation)
    cudaFuncSetAttribute(k2_main, cudaFuncAttributeMaxDynamicSharedMemorySize,
                         K2_SMEM);

    k0_init<<<(BB * DD + 255) / 256, 256>>>();
    k1_classify<<<(BB * NN) / 256, 256>>>(xlab);
    k2_main<<<PBLOCKS, 256, K2_SMEM>>>(x, W1, b1, W2, b2);
    k3_head<<<BB, 1024>>>(Wg1, bg1, Wg2, bg2, out);
}